// round 1
// baseline (speedup 1.0000x reference)
#include <cuda_runtime.h>

// HardBinaryConv: y = conv2d(x, alpha_o * sign(w)), stride 1, pad 1
// x: [32, 256, 56, 56] f32, w: [256, 256, 3, 3] f32, out: [32, 256, 56, 56] f32
//
// Implicit GEMM: M = 32*3136 (n, h*56+w), N = 256 (oc), K = 2304 (c*9 + kh*3 + kw)

#define Cc   256
#define Hh   56
#define Ww   56
#define Oo   256
#define KT   2304      // Cc * 9
#define MIMG 3136      // Hh * Ww
#define NIMG 32

#define BM 128
#define BN 128
#define BK 8
#define NKIT (KT / BK) // 288

// Binarized+scaled weights, [O][K], K contiguous. 2.36 MB device global (no alloc).
__device__ __align__(16) float g_bw[Oo * KT];

// ---------------------------------------------------------------------------
// Kernel 1: per-output-channel alpha = mean|w|, write bw = sign(w) * alpha
// (sign: w > 0 -> +1, else -1, matching 2*(w>0)-1)
// ---------------------------------------------------------------------------
__global__ void binarize_kernel(const float* __restrict__ w) {
    const int o = blockIdx.x;
    const float* wr = w + (size_t)o * KT;
    __shared__ float red[256];
    float s = 0.f;
    for (int i = threadIdx.x; i < KT; i += 256) s += fabsf(wr[i]);
    red[threadIdx.x] = s;
    __syncthreads();
    #pragma unroll
    for (int off = 128; off > 0; off >>= 1) {
        if (threadIdx.x < off) red[threadIdx.x] += red[threadIdx.x + off];
        __syncthreads();
    }
    const float alpha = red[0] * (1.0f / (float)KT);
    float* bwr = g_bw + (size_t)o * KT;
    for (int i = threadIdx.x; i < KT; i += 256)
        bwr[i] = (wr[i] > 0.f) ? alpha : -alpha;
}

// ---------------------------------------------------------------------------
// Kernel 2: implicit-GEMM conv, fp32, 128x128x8 tiles, 8x8 per thread,
// double-buffered shared memory with register prefetch.
// ---------------------------------------------------------------------------
__global__ __launch_bounds__(256, 2)
void conv_kernel(const float* __restrict__ x, float* __restrict__ out) {
    __shared__ float As[2][BK][BM];
    __shared__ float Bs[2][BK][BN];

    const int tid  = threadIdx.x;
    const int mblk = blockIdx.x * BM;
    const int nblk = blockIdx.y * BN;
    const int img  = blockIdx.z;

    const float* xn = x + (size_t)img * (Cc * Hh * Ww);

    // ---- load-phase mapping: 128 (lm) x  {0,4}+j (lk) ----
    const int lm = tid & 127;
    const int lk = (tid >> 7) << 2;   // 0 or 4

    const int  m   = mblk + lm;
    const bool mok = (m < MIMG);
    const int  h   = m / Ww;
    const int  wc  = m - h * Ww;

    const float* brow = g_bw + (size_t)(nblk + lm) * KT + lk;

    // ---- compute-phase mapping: 16 (tx, oc dir) x 16 (ty, m dir) ----
    const int tx = tid & 15;
    const int ty = tid >> 4;
    const int mfrag = ty << 3;
    const int nfrag = tx << 3;

    float acc[8][8];
    #pragma unroll
    for (int i = 0; i < 8; ++i)
        #pragma unroll
        for (int j = 0; j < 8; ++j) acc[i][j] = 0.f;

    // on-the-fly im2col gather for 4 consecutive k at (m, k0+lk..+3)
    auto loadA = [&](int k0, float (&ar)[4]) {
        #pragma unroll
        for (int j = 0; j < 4; ++j) {
            const int k  = k0 + lk + j;
            const int c  = k / 9;
            const int r  = k - c * 9;
            const int kh = r / 3;
            const int kw = r - kh * 3;
            const int hi = h + kh - 1;
            const int wi = wc + kw - 1;
            float v = 0.f;
            if (mok && (unsigned)hi < (unsigned)Hh && (unsigned)wi < (unsigned)Ww)
                v = __ldg(&xn[(c * Hh + hi) * Ww + wi]);
            ar[j] = v;
        }
    };

    // ---- prologue: fill buffer 0 ----
    {
        float areg[4];
        loadA(0, areg);
        const float4 breg = *reinterpret_cast<const float4*>(brow);
        #pragma unroll
        for (int j = 0; j < 4; ++j) As[0][lk + j][lm] = areg[j];
        const float bb[4] = {breg.x, breg.y, breg.z, breg.w};
        #pragma unroll
        for (int j = 0; j < 4; ++j) Bs[0][lk + j][lm] = bb[j];
    }
    __syncthreads();

    // ---- main K loop ----
    for (int it = 0; it < NKIT; ++it) {
        const int  cur     = it & 1;
        const bool hasNext = (it + 1) < NKIT;

        float  aregN[4];
        float4 bregN;
        if (hasNext) {
            loadA((it + 1) * BK, aregN);
            bregN = *reinterpret_cast<const float4*>(brow + (it + 1) * BK);
        }

        #pragma unroll
        for (int kk = 0; kk < BK; ++kk) {
            const float4 a0 = *reinterpret_cast<const float4*>(&As[cur][kk][mfrag]);
            const float4 a1 = *reinterpret_cast<const float4*>(&As[cur][kk][mfrag + 4]);
            const float4 b0 = *reinterpret_cast<const float4*>(&Bs[cur][kk][nfrag]);
            const float4 b1 = *reinterpret_cast<const float4*>(&Bs[cur][kk][nfrag + 4]);
            const float av[8] = {a0.x, a0.y, a0.z, a0.w, a1.x, a1.y, a1.z, a1.w};
            const float bv[8] = {b0.x, b0.y, b0.z, b0.w, b1.x, b1.y, b1.z, b1.w};
            #pragma unroll
            for (int i = 0; i < 8; ++i)
                #pragma unroll
                for (int j = 0; j < 8; ++j)
                    acc[i][j] = fmaf(av[i], bv[j], acc[i][j]);
        }

        if (hasNext) {
            const int nxt = cur ^ 1;
            #pragma unroll
            for (int j = 0; j < 4; ++j) As[nxt][lk + j][lm] = aregN[j];
            const float bb[4] = {bregN.x, bregN.y, bregN.z, bregN.w};
            #pragma unroll
            for (int j = 0; j < 4; ++j) Bs[nxt][lk + j][lm] = bb[j];
        }
        __syncthreads();
    }

    // ---- epilogue: out index is linear in m for fixed (img, oc) ----
    float* outn = out + (size_t)img * Oo * MIMG;
    #pragma unroll
    for (int j = 0; j < 8; ++j) {
        const int oc = nblk + nfrag + j;
        float* orow = outn + (size_t)oc * MIMG;
        #pragma unroll
        for (int i = 0; i < 8; i += 4) {
            const int mo = mblk + mfrag + i;
            if (mo < MIMG) {   // MIMG % 4 == 0, so mo..mo+3 all valid
                const float4 v = make_float4(acc[i][j], acc[i + 1][j],
                                             acc[i + 2][j], acc[i + 3][j]);
                *reinterpret_cast<float4*>(&orow[mo]) = v;
            }
        }
    }
}

// ---------------------------------------------------------------------------
extern "C" void kernel_launch(void* const* d_in, const int* in_sizes, int n_in,
                              void* d_out, int out_size) {
    const float* x = (const float*)d_in[0];
    const float* w = (const float*)d_in[1];
    // Defensive: pick by size in case input order differs.
    if (n_in >= 2 && in_sizes[0] == Oo * KT && in_sizes[1] != Oo * KT) {
        x = (const float*)d_in[1];
        w = (const float*)d_in[0];
    }

    binarize_kernel<<<Oo, 256>>>(w);

    dim3 grid((MIMG + BM - 1) / BM, Oo / BN, NIMG);
    conv_kernel<<<grid, 256>>>(x, (float*)d_out);
}

// round 5
// speedup vs baseline: 11.3920x; 11.3920x over previous
#include <cuda_runtime.h>
#include <cuda_bf16.h>
#include <cuda.h>
#include <stdint.h>

#define Cc   256
#define Hh   56
#define Ww   56
#define Oo   256
#define NIMG 32
#define MIMG 3136          // 56*56
#define KT   2304          // 256*9
#define HP   58            // 1 + 56 + 1
#define WP   64            // 1 + 56 + 7 (pad to 64 so 2 rows = 128 GEMM-N)
#define NCH  36            // K chunks of 64: (kh,kw,cblk)

#define STAGE    65536     // A 32KB + Bhi 16KB + Blo 16KB
#define OFF_A    0
#define OFF_BH   32768
#define OFF_BL   49152
#define NSTG     3
#define SMEM_TOTAL (1024 + 1024 + NSTG*STAGE)

// ---------------- device globals (no runtime alloc allowed) ----------------
__device__ __align__(1024) __nv_bfloat16 g_xhi[(size_t)NIMG*HP*WP*Cc]; // ~61MB
__device__ __align__(1024) __nv_bfloat16 g_xlo[(size_t)NIMG*HP*WP*Cc]; // ~61MB
__device__ __align__(1024) __nv_bfloat16 g_bsign[Oo*KT];  // +-1, k=(kh*3+kw)*256+c
__device__ float g_alpha[Oo];

// ---------------- PTX helpers (all plain-sm_103-legal) ----------------
__device__ __forceinline__ uint32_t smem_u32(const void* p){
    uint32_t a;
    asm("{ .reg .u64 t; cvta.to.shared.u64 t, %1; cvt.u32.u64 %0, t; }" : "=r"(a) : "l"(p));
    return a;
}
#define MBAR_INIT(a,c)  asm volatile("mbarrier.init.shared.b64 [%0], %1;" :: "r"(a), "r"(c) : "memory")
#define MBAR_EXPECT(a,tx) asm volatile("mbarrier.arrive.expect_tx.shared.b64 _, [%0], %1;" :: "r"(a), "r"(tx) : "memory")
#define MBAR_ARRIVE(a)  asm volatile("mbarrier.arrive.shared.b64 _, [%0];" :: "r"(a) : "memory")

#define MBAR_WAIT(mbar, parity) do {                                              \
    uint32_t _m=(mbar), _p=(parity), _d;                                          \
    asm volatile("{\n\t.reg .pred p;\n\t"                                         \
        "mbarrier.try_wait.parity.acquire.cta.shared::cta.b64 p, [%1], %2;\n\t"   \
        "selp.b32 %0, 1, 0, p;\n\t}"                                              \
        : "=r"(_d) : "r"(_m), "r"(_p) : "memory");                                \
    if (!_d) {                                                                    \
        asm volatile("{\n\t.reg .pred P1;\n\t"                                    \
        "WL%=:\n\t"                                                               \
        "mbarrier.try_wait.parity.acquire.cta.shared::cta.b64 P1, [%0], %1, 0x989680;\n\t" \
        "@P1 bra.uni WD%=;\n\t"                                                   \
        "bra.uni WL%=;\n\t"                                                       \
        "WD%=:\n\t}" :: "r"(_m), "r"(_p) : "memory");                             \
    } } while(0)

#define TMA2D(dst, map, c0, c1, mbar) \
    asm volatile("cp.async.bulk.tensor.2d.shared::cta.global.tile.mbarrier::complete_tx::bytes " \
        "[%0], [%1, {%2, %3}], [%4];" \
        :: "r"(dst), "l"(map), "r"(c0), "r"(c1), "r"(mbar) : "memory")
#define TMA3D(dst, map, c0, c1, c2, mbar) \
    asm volatile("cp.async.bulk.tensor.3d.shared::cta.global.tile.mbarrier::complete_tx::bytes " \
        "[%0], [%1, {%2, %3, %4}], [%5];" \
        :: "r"(dst), "l"(map), "r"(c0), "r"(c1), "r"(c2), "r"(mbar) : "memory")

#define LDSM4(r, addr) \
    asm volatile("ldmatrix.sync.aligned.m8n8.x4.shared.b16 {%0,%1,%2,%3}, [%4];" \
        : "=r"((r)[0]), "=r"((r)[1]), "=r"((r)[2]), "=r"((r)[3]) : "r"(addr))

#define MMA(acc, a, b0, b1) \
    asm volatile("mma.sync.aligned.m16n8k16.row.col.f32.bf16.bf16.f32 " \
        "{%0,%1,%2,%3},{%4,%5,%6,%7},{%8,%9},{%0,%1,%2,%3};" \
        : "+f"((acc)[0]), "+f"((acc)[1]), "+f"((acc)[2]), "+f"((acc)[3]) \
        : "r"((a)[0]), "r"((a)[1]), "r"((a)[2]), "r"((a)[3]), "r"(b0), "r"(b1))

// ---------------------------------------------------------------------------
// Kernel 1: alpha = mean|w|; bsign[oc][(kh*3+kw)*256+c] = +-1 bf16
// ---------------------------------------------------------------------------
__global__ void binarize_kernel(const float* __restrict__ w){
    const int o = blockIdx.x;
    const float* wr = w + (size_t)o * KT;
    __shared__ float red[256];
    float s = 0.f;
    for (int i = threadIdx.x; i < KT; i += 256) s += fabsf(wr[i]);
    red[threadIdx.x] = s;
    __syncthreads();
    #pragma unroll
    for (int off = 128; off > 0; off >>= 1){
        if (threadIdx.x < off) red[threadIdx.x] += red[threadIdx.x + off];
        __syncthreads();
    }
    if (threadIdx.x == 0) g_alpha[o] = red[0] * (1.0f / (float)KT);
    const __nv_bfloat16 P1 = __float2bfloat16(1.0f);
    const __nv_bfloat16 M1 = __float2bfloat16(-1.0f);
    for (int i = threadIdx.x; i < KT; i += 256){
        int c = i / 9, r = i - c * 9;                 // w layout [O][C][3][3]
        g_bsign[(size_t)o * KT + r * Cc + c] = (wr[i] > 0.f) ? P1 : M1;
    }
}

// ---------------------------------------------------------------------------
// Kernel 2: NCHW f32 -> padded NHWC bf16 hi/lo. Pads stay .bss-zero forever.
// data x(h,w,c) stored at [img][h+1][w+1][c]
// ---------------------------------------------------------------------------
__global__ void padconvert_kernel(const float* __restrict__ x){
    __shared__ float tile[32][65];
    const int s0 = blockIdx.x * 64, c0 = blockIdx.y * 32, img = blockIdx.z;
    const int t = threadIdx.x;
    #pragma unroll
    for (int j = 0; j < 8; j++){
        int ci = j * 4 + (t >> 6), si = t & 63;
        tile[ci][si] = x[((size_t)(img * Cc + c0 + ci)) * MIMG + s0 + si];
    }
    __syncthreads();
    #pragma unroll
    for (int j = 0; j < 8; j++){
        int si = j * 8 + (t >> 5), ci = t & 31;
        int s = s0 + si, h = s / Ww, wq = s - h * Ww;
        float v = tile[ci][si];
        __nv_bfloat16 hi = __float2bfloat16(v);
        __nv_bfloat16 lo = __float2bfloat16(v - __bfloat162float(hi));
        size_t dst = ((size_t)(img * HP + h + 1) * WP + (wq + 1)) * Cc + c0 + ci;
        g_xhi[dst] = hi;
        g_xlo[dst] = lo;
    }
}

// ---------------------------------------------------------------------------
// Producer: one chunk = (kh, kw, cblk). A: signs [256oc][64k]. B: x hi/lo
// [128p][64c] via 3D box (c=64, w=64, h=2) with OOB-zero for w>=WP.
// ---------------------------------------------------------------------------
__device__ __forceinline__ void issue_chunk(int n, int s, uint32_t data, uint32_t sb,
        int img, int t, const CUtensorMap* mW, const CUtensorMap* mXh, const CUtensorMap* mXl)
{
    const uint32_t st = data + (uint32_t)s * STAGE;
    const uint32_t fb = sb + s * 8;
    const int r = n >> 2, cb = n & 3;
    const int kh = r / 3, kw = r - kh * 3;
    MBAR_EXPECT(fb, STAGE);
    TMA2D(st + OFF_A, mW, n * 64, 0, fb);
    const int hc = img * HP + 2 * t + kh;
    TMA3D(st + OFF_BH, mXh, cb * 64, kw, hc, fb);
    TMA3D(st + OFF_BL, mXl, cb * 64, kw, hc, fb);
}

// ---------------------------------------------------------------------------
// Kernel 3: GEMM via mma.sync bf16. CTA tile: M=256 (oc) x N=128 (p) x K=64.
// 8 warps: warp (wo,wp) owns 64oc x 64p. TMA 3-stage pipeline.
// p = h_local*64 + w' ; valid iff w' < 56. Output m = (2t + h_local)*56 + w'.
// ---------------------------------------------------------------------------
__global__ __launch_bounds__(256, 1)
void conv_mma(const __grid_constant__ CUtensorMap mW,
              const __grid_constant__ CUtensorMap mXh,
              const __grid_constant__ CUtensorMap mXl,
              float* __restrict__ out)
{
    extern __shared__ char smem[];
    const uint32_t sb   = (smem_u32(smem) + 1023u) & ~1023u;
    const uint32_t data = sb + 1024;
    const int tid = threadIdx.x, wid = tid >> 5, l = tid & 31;
    const int t = blockIdx.x, img = blockIdx.y;
    const int wo = wid >> 1, wp = wid & 1;

    // full[s] = sb + s*8 ; empty[s] = sb + 24 + s*8
    if (tid == 0){
        #pragma unroll
        for (int s = 0; s < NSTG; s++){ MBAR_INIT(sb + s*8, 1); MBAR_INIT(sb + 24 + s*8, 256); }
    }
    __syncthreads();

    // ---- per-thread ldmatrix offsets: UNSWIZZLED base + XOR mask.
    // SW128 swizzle: addr = (row*128 + col) ^ ((row&7)*16). The k-step offset
    // (ks*32) must be added to the base BEFORE the XOR (col+ks*32 < 128, so
    // the mask is row-only and the add can never corrupt it).
    const int mat = l >> 3, lr = l & 7;
    uint32_t abase[4], amask[4], bbase[4], bmask[4];
    #pragma unroll
    for (int mf = 0; mf < 4; mf++){
        uint32_t row = wo * 64 + mf * 16 + (mat & 1) * 8 + lr;   // oc row
        abase[mf] = row * 128 + (mat >> 1) * 16;
        amask[mf] = (row & 7) * 16;
    }
    #pragma unroll
    for (int q = 0; q < 4; q++){
        uint32_t row = wp * 64 + (2 * q + (mat >> 1)) * 8 + lr;  // p row
        bbase[q] = row * 128 + (mat & 1) * 16;
        bmask[q] = (row & 7) * 16;
    }

    float acc[4][8][4];
    #pragma unroll
    for (int i = 0; i < 4; i++)
        #pragma unroll
        for (int j = 0; j < 8; j++)
            #pragma unroll
            for (int k = 0; k < 4; k++) acc[i][j][k] = 0.f;

    // ---- prologue: fill all 3 stages ----
    if (tid == 0){
        #pragma unroll
        for (int n = 0; n < NSTG; n++) issue_chunk(n, n, data, sb, img, t, &mW, &mXh, &mXl);
    }

    int cs = 0, cph = 0;             // consumer stage/phase
    int pn = NSTG, ps = 0, pph = 0;  // producer next-chunk/stage/phase

    for (int c = 0; c < NCH; c++){
        MBAR_WAIT(sb + cs * 8, cph);
        const uint32_t stA  = data + (uint32_t)cs * STAGE;
        const uint32_t stBH = stA + OFF_BH, stBL = stA + OFF_BL;

        #pragma unroll
        for (int ks = 0; ks < 4; ks++){
            uint32_t ra[4][4], rbh[4][4], rbl[4][4];
            #pragma unroll
            for (int mf = 0; mf < 4; mf++)
                LDSM4(ra[mf],  stA  + ((abase[mf] + ks * 32) ^ amask[mf]));
            #pragma unroll
            for (int q = 0; q < 4; q++)
                LDSM4(rbh[q], stBH + ((bbase[q] + ks * 32) ^ bmask[q]));
            #pragma unroll
            for (int q = 0; q < 4; q++)
                LDSM4(rbl[q], stBL + ((bbase[q] + ks * 32) ^ bmask[q]));
            #pragma unroll
            for (int mf = 0; mf < 4; mf++)
                #pragma unroll
                for (int nf = 0; nf < 8; nf++)
                    MMA(acc[mf][nf], ra[mf], rbh[nf >> 1][(nf & 1) * 2], rbh[nf >> 1][(nf & 1) * 2 + 1]);
            #pragma unroll
            for (int mf = 0; mf < 4; mf++)
                #pragma unroll
                for (int nf = 0; nf < 8; nf++)
                    MMA(acc[mf][nf], ra[mf], rbl[nf >> 1][(nf & 1) * 2], rbl[nf >> 1][(nf & 1) * 2 + 1]);
        }

        MBAR_ARRIVE(sb + 24 + cs * 8);
        cs++; if (cs == NSTG){ cs = 0; cph ^= 1; }

        if (tid == 0 && pn < NCH){
            MBAR_WAIT(sb + 24 + ps * 8, pph);      // stage drained by all consumers
            issue_chunk(pn, ps, data, sb, img, t, &mW, &mXh, &mXl);
            pn++; ps++; if (ps == NSTG){ ps = 0; pph ^= 1; }
        }
    }

    // ---- epilogue: fp32 alpha scale, mask junk columns (w' >= 56) ----
    float* outp = out + (size_t)img * Oo * MIMG;
    #pragma unroll
    for (int mf = 0; mf < 4; mf++){
        const int oc0 = wo * 64 + mf * 16 + (l >> 2);
        const float a0 = __ldg(&g_alpha[oc0]);
        const float a1 = __ldg(&g_alpha[oc0 + 8]);
        #pragma unroll
        for (int nf = 0; nf < 8; nf++){
            const int p = wp * 64 + nf * 8 + 2 * (l & 3);
            const int wloc = p & 63;
            if (wloc < Ww){
                const int m = (2 * t + (p >> 6)) * Ww + wloc;
                float2 v0 = make_float2(acc[mf][nf][0] * a0, acc[mf][nf][1] * a0);
                float2 v1 = make_float2(acc[mf][nf][2] * a1, acc[mf][nf][3] * a1);
                *reinterpret_cast<float2*>(outp + (size_t)oc0 * MIMG + m)       = v0;
                *reinterpret_cast<float2*>(outp + (size_t)(oc0 + 8) * MIMG + m) = v1;
            }
        }
    }
}

// ---------------------------------------------------------------------------
typedef CUresult (*PFN_tmEnc)(CUtensorMap*, CUtensorMapDataType, cuuint32_t, void*,
                              const cuuint64_t*, const cuuint64_t*, const cuuint32_t*,
                              const cuuint32_t*, CUtensorMapInterleave, CUtensorMapSwizzle,
                              CUtensorMapL2promotion, CUtensorMapFloatOOBfill);

extern "C" void kernel_launch(void* const* d_in, const int* in_sizes, int n_in,
                              void* d_out, int out_size){
    const float* x = (const float*)d_in[0];
    const float* w = (const float*)d_in[1];
    if (n_in >= 2 && in_sizes[0] == Oo * KT && in_sizes[1] != Oo * KT){
        x = (const float*)d_in[1];
        w = (const float*)d_in[0];
    }

    void *pxh = nullptr, *pxl = nullptr, *pw = nullptr;
    cudaGetSymbolAddress(&pxh, g_xhi);
    cudaGetSymbolAddress(&pxl, g_xlo);
    cudaGetSymbolAddress(&pw,  g_bsign);

    PFN_tmEnc enc = nullptr;
    cudaDriverEntryPointQueryResult qr;
    cudaGetDriverEntryPointByVersion("cuTensorMapEncodeTiled", (void**)&enc, 12000,
                                     cudaEnableDefault, &qr);

    CUtensorMap mW, mXh, mXl;
    {   // signs: 2D [k=2304][oc=256], box (64, 256), SW128
        cuuint64_t dim[2]   = {KT, Oo};
        cuuint64_t strd[1]  = {KT * 2};
        cuuint32_t box[2]   = {64, 256};
        cuuint32_t est[2]   = {1, 1};
        enc(&mW, CU_TENSOR_MAP_DATA_TYPE_BFLOAT16, 2, pw, dim, strd, box, est,
            CU_TENSOR_MAP_INTERLEAVE_NONE, CU_TENSOR_MAP_SWIZZLE_128B,
            CU_TENSOR_MAP_L2_PROMOTION_L2_128B, CU_TENSOR_MAP_FLOAT_OOB_FILL_NONE);
    }
    {   // x planes: 3D [c=256][w=64][img*h=1856], box (64, 64, 2), SW128
        cuuint64_t dim[3]   = {Cc, WP, (cuuint64_t)NIMG * HP};
        cuuint64_t strd[2]  = {Cc * 2, (cuuint64_t)WP * Cc * 2};
        cuuint32_t box[3]   = {64, 64, 2};
        cuuint32_t est[3]   = {1, 1, 1};
        enc(&mXh, CU_TENSOR_MAP_DATA_TYPE_BFLOAT16, 3, pxh, dim, strd, box, est,
            CU_TENSOR_MAP_INTERLEAVE_NONE, CU_TENSOR_MAP_SWIZZLE_128B,
            CU_TENSOR_MAP_L2_PROMOTION_L2_128B, CU_TENSOR_MAP_FLOAT_OOB_FILL_NONE);
        enc(&mXl, CU_TENSOR_MAP_DATA_TYPE_BFLOAT16, 3, pxl, dim, strd, box, est,
            CU_TENSOR_MAP_INTERLEAVE_NONE, CU_TENSOR_MAP_SWIZZLE_128B,
            CU_TENSOR_MAP_L2_PROMOTION_L2_128B, CU_TENSOR_MAP_FLOAT_OOB_FILL_NONE);
    }

    cudaFuncSetAttribute(conv_mma, cudaFuncAttributeMaxDynamicSharedMemorySize, SMEM_TOTAL);

    binarize_kernel<<<Oo, 256>>>(w);
    padconvert_kernel<<<dim3(49, 8, NIMG), 256>>>(x);
    conv_mma<<<dim3(28, NIMG), 256, SMEM_TOTAL>>>(mW, mXh, mXl, (float*)d_out);
}

// round 7
// speedup vs baseline: 19.8879x; 1.7458x over previous
#include <cuda_runtime.h>
#include <cuda_fp16.h>
#include <cuda.h>
#include <stdint.h>

#define Cc   256
#define Hh   56
#define Ww   56
#define Oo   256
#define NIMG 32
#define MIMG 3136          // 56*56
#define KT   2304          // 256*9
#define HP   58            // 1 + 56 + 1
#define WP   64            // 1 + 56 + 7 (pad to 64 so 2 rows = 128 GEMM-N)
#define NCH  36            // K chunks of 64: (kh,kw,cblk)

#define STAGE    49152     // A 32KB + B 16KB
#define OFF_A    0
#define OFF_B    32768
#define NSTG     4
#define SMEM_TOTAL (1024 + 1024 + NSTG*STAGE)

// ---------------- device globals (no runtime alloc allowed) ----------------
__device__ __align__(1024) __half g_xh[(size_t)NIMG*HP*WP*Cc]; // ~61MB fp16 plane
__device__ __align__(1024) __half g_bsign[Oo*KT];  // +-1, k=(kh*3+kw)*256+c
__device__ float g_alpha[Oo];

// ---------------- PTX helpers (all plain-sm_103-legal) ----------------
__device__ __forceinline__ uint32_t smem_u32(const void* p){
    uint32_t a;
    asm("{ .reg .u64 t; cvta.to.shared.u64 t, %1; cvt.u32.u64 %0, t; }" : "=r"(a) : "l"(p));
    return a;
}
#define MBAR_INIT(a,c)  asm volatile("mbarrier.init.shared.b64 [%0], %1;" :: "r"(a), "r"(c) : "memory")
#define MBAR_EXPECT(a,tx) asm volatile("mbarrier.arrive.expect_tx.shared.b64 _, [%0], %1;" :: "r"(a), "r"(tx) : "memory")
#define MBAR_ARRIVE(a)  asm volatile("mbarrier.arrive.shared.b64 _, [%0];" :: "r"(a) : "memory")

#define MBAR_WAIT(mbar, parity) do {                                              \
    uint32_t _m=(mbar), _p=(parity), _d;                                          \
    asm volatile("{\n\t.reg .pred p;\n\t"                                         \
        "mbarrier.try_wait.parity.acquire.cta.shared::cta.b64 p, [%1], %2;\n\t"   \
        "selp.b32 %0, 1, 0, p;\n\t}"                                              \
        : "=r"(_d) : "r"(_m), "r"(_p) : "memory");                                \
    if (!_d) {                                                                    \
        asm volatile("{\n\t.reg .pred P1;\n\t"                                    \
        "WL%=:\n\t"                                                               \
        "mbarrier.try_wait.parity.acquire.cta.shared::cta.b64 P1, [%0], %1, 0x989680;\n\t" \
        "@P1 bra.uni WD%=;\n\t"                                                   \
        "bra.uni WL%=;\n\t"                                                       \
        "WD%=:\n\t}" :: "r"(_m), "r"(_p) : "memory");                             \
    } } while(0)

#define TMA2D(dst, map, c0, c1, mbar) \
    asm volatile("cp.async.bulk.tensor.2d.shared::cta.global.tile.mbarrier::complete_tx::bytes " \
        "[%0], [%1, {%2, %3}], [%4];" \
        :: "r"(dst), "l"(map), "r"(c0), "r"(c1), "r"(mbar) : "memory")
#define TMA3D(dst, map, c0, c1, c2, mbar) \
    asm volatile("cp.async.bulk.tensor.3d.shared::cta.global.tile.mbarrier::complete_tx::bytes " \
        "[%0], [%1, {%2, %3, %4}], [%5];" \
        :: "r"(dst), "l"(map), "r"(c0), "r"(c1), "r"(c2), "r"(mbar) : "memory")

#define LDSM4(r, addr) \
    asm volatile("ldmatrix.sync.aligned.m8n8.x4.shared.b16 {%0,%1,%2,%3}, [%4];" \
        : "=r"((r)[0]), "=r"((r)[1]), "=r"((r)[2]), "=r"((r)[3]) : "r"(addr))

#define MMA(acc, a, b0, b1) \
    asm volatile("mma.sync.aligned.m16n8k16.row.col.f32.f16.f16.f32 " \
        "{%0,%1,%2,%3},{%4,%5,%6,%7},{%8,%9},{%0,%1,%2,%3};" \
        : "+f"((acc)[0]), "+f"((acc)[1]), "+f"((acc)[2]), "+f"((acc)[3]) \
        : "r"((a)[0]), "r"((a)[1]), "r"((a)[2]), "r"((a)[3]), "r"(b0), "r"(b1))

// ---------------------------------------------------------------------------
// Kernel 1: alpha = mean|w|; bsign[oc][(kh*3+kw)*256+c] = +-1 fp16
// ---------------------------------------------------------------------------
__global__ void binarize_kernel(const float* __restrict__ w){
    const int o = blockIdx.x;
    const float* wr = w + (size_t)o * KT;
    __shared__ float red[256];
    float s = 0.f;
    for (int i = threadIdx.x; i < KT; i += 256) s += fabsf(wr[i]);
    red[threadIdx.x] = s;
    __syncthreads();
    #pragma unroll
    for (int off = 128; off > 0; off >>= 1){
        if (threadIdx.x < off) red[threadIdx.x] += red[threadIdx.x + off];
        __syncthreads();
    }
    if (threadIdx.x == 0) g_alpha[o] = red[0] * (1.0f / (float)KT);
    const __half P1 = __float2half(1.0f);
    const __half M1 = __float2half(-1.0f);
    for (int i = threadIdx.x; i < KT; i += 256){
        int c = i / 9, r = i - c * 9;                 // w layout [O][C][3][3]
        g_bsign[(size_t)o * KT + r * Cc + c] = (wr[i] > 0.f) ? P1 : M1;
    }
}

// ---------------------------------------------------------------------------
// Kernel 2: NCHW f32 -> padded NHWC fp16. Pads stay .bss-zero forever.
// data x(h,w,c) stored at [img][h+1][w+1][c]
// ---------------------------------------------------------------------------
__global__ void padconvert_kernel(const float* __restrict__ x){
    __shared__ float tile[32][65];
    const int s0 = blockIdx.x * 64, c0 = blockIdx.y * 32, img = blockIdx.z;
    const int t = threadIdx.x;
    #pragma unroll
    for (int j = 0; j < 8; j++){
        int ci = j * 4 + (t >> 6), si = t & 63;
        tile[ci][si] = x[((size_t)(img * Cc + c0 + ci)) * MIMG + s0 + si];
    }
    __syncthreads();
    #pragma unroll
    for (int j = 0; j < 8; j++){
        int si = j * 8 + (t >> 5), ci = t & 31;
        int s = s0 + si, h = s / Ww, wq = s - h * Ww;
        size_t dst = ((size_t)(img * HP + h + 1) * WP + (wq + 1)) * Cc + c0 + ci;
        g_xh[dst] = __float2half(tile[ci][si]);
    }
}

// ---------------------------------------------------------------------------
// Producer: one chunk = (kh, kw, cblk). A: signs [256oc][64k]. B: x fp16
// [128p][64c] via 3D box (c=64, w=64, h=2) with OOB-zero for w>=WP.
// ---------------------------------------------------------------------------
__device__ __forceinline__ void issue_chunk(int n, int s, uint32_t data, uint32_t sb,
        int img, int t, const CUtensorMap* mW, const CUtensorMap* mX)
{
    const uint32_t st = data + (uint32_t)s * STAGE;
    const uint32_t fb = sb + s * 8;
    const int r = n >> 2, cb = n & 3;
    const int kh = r / 3, kw = r - kh * 3;
    MBAR_EXPECT(fb, STAGE);
    TMA2D(st + OFF_A, mW, n * 64, 0, fb);
    const int hc = img * HP + 2 * t + kh;
    TMA3D(st + OFF_B, mX, cb * 64, kw, hc, fb);
}

// ---------------------------------------------------------------------------
// Kernel 3: GEMM via mma.sync fp16. CTA tile: M=256 (oc) x N=128 (p) x K=64.
// 8 warps: warp (wo,wp) owns 64oc x 64p. TMA 4-stage pipeline.
// p = h_local*64 + w' ; valid iff w' < 56. Output m = (2t + h_local)*56 + w'.
// ---------------------------------------------------------------------------
__global__ __launch_bounds__(256, 1)
void conv_mma(const __grid_constant__ CUtensorMap mW,
              const __grid_constant__ CUtensorMap mX,
              float* __restrict__ out)
{
    extern __shared__ char smem[];
    const uint32_t sb   = (smem_u32(smem) + 1023u) & ~1023u;
    const uint32_t data = sb + 1024;
    const int tid = threadIdx.x, wid = tid >> 5, l = tid & 31;
    const int t = blockIdx.x, img = blockIdx.y;
    const int wo = wid >> 1, wp = wid & 1;

    // full[s] = sb + s*8 ; empty[s] = sb + 32 + s*8
    if (tid == 0){
        #pragma unroll
        for (int s = 0; s < NSTG; s++){ MBAR_INIT(sb + s*8, 1); MBAR_INIT(sb + 32 + s*8, 256); }
    }
    __syncthreads();

    // ---- per-thread ldmatrix offsets: UNSWIZZLED base + XOR mask.
    // SW128: addr = (row*128 + col) ^ ((row&7)*16); add ks*32 BEFORE the XOR.
    const int mat = l >> 3, lr = l & 7;
    uint32_t abase[4], amask[4], bbase[4], bmask[4];
    #pragma unroll
    for (int mf = 0; mf < 4; mf++){
        uint32_t row = wo * 64 + mf * 16 + (mat & 1) * 8 + lr;   // oc row
        abase[mf] = row * 128 + (mat >> 1) * 16;
        amask[mf] = (row & 7) * 16;
    }
    #pragma unroll
    for (int q = 0; q < 4; q++){
        uint32_t row = wp * 64 + (2 * q + (mat >> 1)) * 8 + lr;  // p row
        bbase[q] = row * 128 + (mat & 1) * 16;
        bmask[q] = (row & 7) * 16;
    }

    float acc[4][8][4];
    #pragma unroll
    for (int i = 0; i < 4; i++)
        #pragma unroll
        for (int j = 0; j < 8; j++)
            #pragma unroll
            for (int k = 0; k < 4; k++) acc[i][j][k] = 0.f;

    // ---- prologue: fill all stages ----
    if (tid == 0){
        #pragma unroll
        for (int n = 0; n < NSTG; n++) issue_chunk(n, n, data, sb, img, t, &mW, &mX);
    }

    int cs = 0, cph = 0;             // consumer stage/phase
    int pn = NSTG, ps = 0, pph = 0;  // producer next-chunk/stage/phase

    for (int c = 0; c < NCH; c++){
        MBAR_WAIT(sb + cs * 8, cph);
        const uint32_t stA = data + (uint32_t)cs * STAGE;
        const uint32_t stB = stA + OFF_B;

        #pragma unroll
        for (int ks = 0; ks < 4; ks++){
            uint32_t ra[4][4], rb[4][4];
            #pragma unroll
            for (int mf = 0; mf < 4; mf++)
                LDSM4(ra[mf], stA + ((abase[mf] + ks * 32) ^ amask[mf]));
            #pragma unroll
            for (int q = 0; q < 4; q++)
                LDSM4(rb[q], stB + ((bbase[q] + ks * 32) ^ bmask[q]));
            #pragma unroll
            for (int mf = 0; mf < 4; mf++)
                #pragma unroll
                for (int nf = 0; nf < 8; nf++)
                    MMA(acc[mf][nf], ra[mf], rb[nf >> 1][(nf & 1) * 2], rb[nf >> 1][(nf & 1) * 2 + 1]);
        }

        MBAR_ARRIVE(sb + 32 + cs * 8);
        cs++; if (cs == NSTG){ cs = 0; cph ^= 1; }

        if (tid == 0 && pn < NCH){
            MBAR_WAIT(sb + 32 + ps * 8, pph);      // stage drained by all consumers
            issue_chunk(pn, ps, data, sb, img, t, &mW, &mX);
            pn++; ps++; if (ps == NSTG){ ps = 0; pph ^= 1; }
        }
    }

    // ---- epilogue: fp32 alpha scale, mask junk columns (w' >= 56) ----
    float* outp = out + (size_t)img * Oo * MIMG;
    #pragma unroll
    for (int mf = 0; mf < 4; mf++){
        const int oc0 = wo * 64 + mf * 16 + (l >> 2);
        const float a0 = __ldg(&g_alpha[oc0]);
        const float a1 = __ldg(&g_alpha[oc0 + 8]);
        #pragma unroll
        for (int nf = 0; nf < 8; nf++){
            const int p = wp * 64 + nf * 8 + 2 * (l & 3);
            const int wloc = p & 63;
            if (wloc < Ww){
                const int m = (2 * t + (p >> 6)) * Ww + wloc;
                float2 v0 = make_float2(acc[mf][nf][0] * a0, acc[mf][nf][1] * a0);
                float2 v1 = make_float2(acc[mf][nf][2] * a1, acc[mf][nf][3] * a1);
                *reinterpret_cast<float2*>(outp + (size_t)oc0 * MIMG + m)       = v0;
                *reinterpret_cast<float2*>(outp + (size_t)(oc0 + 8) * MIMG + m) = v1;
            }
        }
    }
}

// ---------------------------------------------------------------------------
typedef CUresult (*PFN_tmEnc)(CUtensorMap*, CUtensorMapDataType, cuuint32_t, void*,
                              const cuuint64_t*, const cuuint64_t*, const cuuint32_t*,
                              const cuuint32_t*, CUtensorMapInterleave, CUtensorMapSwizzle,
                              CUtensorMapL2promotion, CUtensorMapFloatOOBfill);

extern "C" void kernel_launch(void* const* d_in, const int* in_sizes, int n_in,
                              void* d_out, int out_size){
    const float* x = (const float*)d_in[0];
    const float* w = (const float*)d_in[1];
    if (n_in >= 2 && in_sizes[0] == Oo * KT && in_sizes[1] != Oo * KT){
        x = (const float*)d_in[1];
        w = (const float*)d_in[0];
    }

    void *pxh = nullptr, *pw = nullptr;
    cudaGetSymbolAddress(&pxh, g_xh);
    cudaGetSymbolAddress(&pw,  g_bsign);

    PFN_tmEnc enc = nullptr;
    cudaDriverEntryPointQueryResult qr;
    cudaGetDriverEntryPointByVersion("cuTensorMapEncodeTiled", (void**)&enc, 12000,
                                     cudaEnableDefault, &qr);

    CUtensorMap mW, mX;
    {   // signs: 2D [k=2304][oc=256], box (64, 256), SW128
        cuuint64_t dim[2]   = {KT, Oo};
        cuuint64_t strd[1]  = {KT * 2};
        cuuint32_t box[2]   = {64, 256};
        cuuint32_t est[2]   = {1, 1};
        enc(&mW, CU_TENSOR_MAP_DATA_TYPE_FLOAT16, 2, pw, dim, strd, box, est,
            CU_TENSOR_MAP_INTERLEAVE_NONE, CU_TENSOR_MAP_SWIZZLE_128B,
            CU_TENSOR_MAP_L2_PROMOTION_L2_128B, CU_TENSOR_MAP_FLOAT_OOB_FILL_NONE);
    }
    {   // x plane: 3D [c=256][w=64][img*h=1856], box (64, 64, 2), SW128
        cuuint64_t dim[3]   = {Cc, WP, (cuuint64_t)NIMG * HP};
        cuuint64_t strd[2]  = {Cc * 2, (cuuint64_t)WP * Cc * 2};
        cuuint32_t box[3]   = {64, 64, 2};
        cuuint32_t est[3]   = {1, 1, 1};
        enc(&mX, CU_TENSOR_MAP_DATA_TYPE_FLOAT16, 3, pxh, dim, strd, box, est,
            CU_TENSOR_MAP_INTERLEAVE_NONE, CU_TENSOR_MAP_SWIZZLE_128B,
            CU_TENSOR_MAP_L2_PROMOTION_L2_128B, CU_TENSOR_MAP_FLOAT_OOB_FILL_NONE);
    }

    cudaFuncSetAttribute(conv_mma, cudaFuncAttributeMaxDynamicSharedMemorySize, SMEM_TOTAL);

    binarize_kernel<<<Oo, 256>>>(w);
    padconvert_kernel<<<dim3(49, 8, NIMG), 256>>>(x);
    conv_mma<<<dim3(28, NIMG), 256, SMEM_TOTAL>>>(mW, mX, (float*)d_out);
}

// round 9
// speedup vs baseline: 20.0088x; 1.0061x over previous
#include <cuda_runtime.h>
#include <cuda_fp16.h>
#include <cuda.h>
#include <stdint.h>

#define Cc   256
#define Hh   56
#define Ww   56
#define Oo   256
#define NIMG 32
#define MIMG 3136          // 56*56
#define KT   2304          // 256*9
#define HP   58            // 1 + 56 + 1
#define WP   64            // 1 + 56 + 7 (pad to 64 so 2 rows = 128 smem rows)
#define NCH  36            // K chunks of 64: (kh,kw,cblk)

#define STAGE    49152     // A 32KB + B 16KB
#define OFF_A    0
#define OFF_B    32768
#define NSTG     4
#define SMEM_TOTAL (1024 + 1024 + NSTG*STAGE)

// ---------------- device globals (no runtime alloc allowed) ----------------
__device__ __align__(1024) __half g_xh[(size_t)NIMG*HP*WP*Cc]; // ~61MB fp16 plane
__device__ __align__(1024) __half g_bsign[Oo*KT];  // +-1, k=(kh*3+kw)*256+c
__device__ float g_alpha[Oo];

// ---------------- PTX helpers (all plain-sm_103-legal) ----------------
__device__ __forceinline__ uint32_t smem_u32(const void* p){
    uint32_t a;
    asm("{ .reg .u64 t; cvta.to.shared.u64 t, %1; cvt.u32.u64 %0, t; }" : "=r"(a) : "l"(p));
    return a;
}
#define MBAR_INIT(a,c)  asm volatile("mbarrier.init.shared.b64 [%0], %1;" :: "r"(a), "r"(c) : "memory")
#define MBAR_EXPECT(a,tx) asm volatile("mbarrier.arrive.expect_tx.shared.b64 _, [%0], %1;" :: "r"(a), "r"(tx) : "memory")
#define MBAR_ARRIVE(a)  asm volatile("mbarrier.arrive.shared.b64 _, [%0];" :: "r"(a) : "memory")

#define MBAR_WAIT(mbar, parity) do {                                              \
    uint32_t _m=(mbar), _p=(parity), _d;                                          \
    asm volatile("{\n\t.reg .pred p;\n\t"                                         \
        "mbarrier.try_wait.parity.acquire.cta.shared::cta.b64 p, [%1], %2;\n\t"   \
        "selp.b32 %0, 1, 0, p;\n\t}"                                              \
        : "=r"(_d) : "r"(_m), "r"(_p) : "memory");                                \
    if (!_d) {                                                                    \
        asm volatile("{\n\t.reg .pred P1;\n\t"                                    \
        "WL%=:\n\t"                                                               \
        "mbarrier.try_wait.parity.acquire.cta.shared::cta.b64 P1, [%0], %1, 0x989680;\n\t" \
        "@P1 bra.uni WD%=;\n\t"                                                   \
        "bra.uni WL%=;\n\t"                                                       \
        "WD%=:\n\t}" :: "r"(_m), "r"(_p) : "memory");                             \
    } } while(0)

#define TMA2D(dst, map, c0, c1, mbar) \
    asm volatile("cp.async.bulk.tensor.2d.shared::cta.global.tile.mbarrier::complete_tx::bytes " \
        "[%0], [%1, {%2, %3}], [%4];" \
        :: "r"(dst), "l"(map), "r"(c0), "r"(c1), "r"(mbar) : "memory")
#define TMA3D(dst, map, c0, c1, c2, mbar) \
    asm volatile("cp.async.bulk.tensor.3d.shared::cta.global.tile.mbarrier::complete_tx::bytes " \
        "[%0], [%1, {%2, %3, %4}], [%5];" \
        :: "r"(dst), "l"(map), "r"(c0), "r"(c1), "r"(c2), "r"(mbar) : "memory")

#define LDSM4(r, addr) \
    asm volatile("ldmatrix.sync.aligned.m8n8.x4.shared.b16 {%0,%1,%2,%3}, [%4];" \
        : "=r"((r)[0]), "=r"((r)[1]), "=r"((r)[2]), "=r"((r)[3]) : "r"(addr))

#define MMA(acc, a, b0, b1) \
    asm volatile("mma.sync.aligned.m16n8k16.row.col.f32.f16.f16.f32 " \
        "{%0,%1,%2,%3},{%4,%5,%6,%7},{%8,%9},{%0,%1,%2,%3};" \
        : "+f"((acc)[0]), "+f"((acc)[1]), "+f"((acc)[2]), "+f"((acc)[3]) \
        : "r"((a)[0]), "r"((a)[1]), "r"((a)[2]), "r"((a)[3]), "r"(b0), "r"(b1))

// ---------------------------------------------------------------------------
// Fused prologue. z < NIMG : padconvert blocks (x 49, y 8).
//                 z == NIMG: binarize, oc = bx*8 + by (first 256 of 392).
// ---------------------------------------------------------------------------
__global__ void prologue_kernel(const float* __restrict__ x, const float* __restrict__ w){
    if (blockIdx.z == NIMG){
        const int o = blockIdx.x * 8 + blockIdx.y;
        if (o >= Oo) return;
        const float* wr = w + (size_t)o * KT;
        __shared__ float red[256];
        float s = 0.f;
        for (int i = threadIdx.x; i < KT; i += 256) s += fabsf(wr[i]);
        red[threadIdx.x] = s;
        __syncthreads();
        #pragma unroll
        for (int off = 128; off > 0; off >>= 1){
            if (threadIdx.x < off) red[threadIdx.x] += red[threadIdx.x + off];
            __syncthreads();
        }
        if (threadIdx.x == 0) g_alpha[o] = red[0] * (1.0f / (float)KT);
        const __half P1 = __float2half(1.0f);
        const __half M1 = __float2half(-1.0f);
        for (int i = threadIdx.x; i < KT; i += 256){
            int c = i / 9, r = i - c * 9;                 // w layout [O][C][3][3]
            g_bsign[(size_t)o * KT + r * Cc + c] = (wr[i] > 0.f) ? P1 : M1;
        }
        return;
    }
    // ---- NCHW f32 -> padded NHWC fp16; pads stay .bss-zero forever ----
    __shared__ float tile[32][65];
    const int s0 = blockIdx.x * 64, c0 = blockIdx.y * 32, img = blockIdx.z;
    const int t = threadIdx.x;
    #pragma unroll
    for (int j = 0; j < 8; j++){
        int ci = j * 4 + (t >> 6), si = t & 63;
        tile[ci][si] = x[((size_t)(img * Cc + c0 + ci)) * MIMG + s0 + si];
    }
    __syncthreads();
    #pragma unroll
    for (int j = 0; j < 8; j++){
        int si = j * 8 + (t >> 5), ci = t & 31;
        int s = s0 + si, h = s / Ww, wq = s - h * Ww;
        size_t dst = ((size_t)(img * HP + h + 1) * WP + (wq + 1)) * Cc + c0 + ci;
        g_xh[dst] = __float2half(tile[ci][si]);
    }
}

// ---------------------------------------------------------------------------
// Producer: one chunk = (kh, kw, cblk). A: signs [256oc][64k]. B: x fp16
// [128p][64c] via 3D box (c=64, w=64, h=2) with OOB-zero for w>=WP.
// ---------------------------------------------------------------------------
__device__ __forceinline__ void issue_chunk(int n, int s, uint32_t data, uint32_t sb,
        int img, int t, const CUtensorMap* mW, const CUtensorMap* mX)
{
    const uint32_t st = data + (uint32_t)s * STAGE;
    const uint32_t fb = sb + s * 8;
    const int r = n >> 2, cb = n & 3;
    const int kh = r / 3, kw = r - kh * 3;
    MBAR_EXPECT(fb, STAGE);
    TMA2D(st + OFF_A, mW, n * 64, 0, fb);
    const int hc = img * HP + 2 * t + kh;
    TMA3D(st + OFF_B, mX, cb * 64, kw, hc, fb);
}

// ---------------------------------------------------------------------------
// Kernel 3: GEMM via mma.sync fp16. CTA tile: M=256 (oc) x N=112 (valid p),
// K=64. 8 warps: warp (wo,wp) owns 64oc x 56p. TMA 4-stage pipeline.
// Smem B has 128 rows; valid outputs are rows wp*64 + 0..55 (w' = 0..55).
// 7 n-frags x n=8 = 56 = exact image width -> zero junk MMAs, stores
// unconditional. Output m = (2t + wp)*56 + w'.
// ---------------------------------------------------------------------------
__global__ __launch_bounds__(256, 1)
void conv_mma(const __grid_constant__ CUtensorMap mW,
              const __grid_constant__ CUtensorMap mX,
              float* __restrict__ out)
{
    extern __shared__ char smem[];
    const uint32_t sb   = (smem_u32(smem) + 1023u) & ~1023u;
    const uint32_t data = sb + 1024;
    const int tid = threadIdx.x, wid = tid >> 5, l = tid & 31;
    const int t = blockIdx.x, img = blockIdx.y;
    const int wo = wid >> 1, wp = wid & 1;

    // full[s] = sb + s*8 ; empty[s] = sb + 32 + s*8
    if (tid == 0){
        #pragma unroll
        for (int s = 0; s < NSTG; s++){ MBAR_INIT(sb + s*8, 1); MBAR_INIT(sb + 32 + s*8, 256); }
    }
    __syncthreads();

    // ---- per-thread ldmatrix offsets: UNSWIZZLED base + XOR mask.
    // SW128: addr = (row*128 + col) ^ ((row&7)*16); add ks*32 BEFORE the XOR.
    const int mat = l >> 3, lr = l & 7;
    uint32_t abase[4], amask[4], bbase[4], bmask[4];
    #pragma unroll
    for (int mf = 0; mf < 4; mf++){
        uint32_t row = wo * 64 + mf * 16 + (mat & 1) * 8 + lr;   // oc row
        abase[mf] = row * 128 + (mat >> 1) * 16;
        amask[mf] = (row & 7) * 16;
    }
    #pragma unroll
    for (int q = 0; q < 4; q++){
        uint32_t row = wp * 64 + (2 * q + (mat >> 1)) * 8 + lr;  // p row
        bbase[q] = row * 128 + (mat & 1) * 16;
        bmask[q] = (row & 7) * 16;
    }

    float acc[4][7][4];
    #pragma unroll
    for (int i = 0; i < 4; i++)
        #pragma unroll
        for (int j = 0; j < 7; j++)
            #pragma unroll
            for (int k = 0; k < 4; k++) acc[i][j][k] = 0.f;

    // ---- prologue: fill all stages ----
    if (tid == 0){
        #pragma unroll
        for (int n = 0; n < NSTG; n++) issue_chunk(n, n, data, sb, img, t, &mW, &mX);
    }

    int cs = 0, cph = 0;             // consumer stage/phase
    int pn = NSTG, ps = 0, pph = 0;  // producer next-chunk/stage/phase

    for (int c = 0; c < NCH; c++){
        MBAR_WAIT(sb + cs * 8, cph);
        const uint32_t stA = data + (uint32_t)cs * STAGE;
        const uint32_t stB = stA + OFF_B;

        #pragma unroll
        for (int ks = 0; ks < 4; ks++){
            uint32_t ra[4][4], rb[4][4];
            #pragma unroll
            for (int mf = 0; mf < 4; mf++)
                LDSM4(ra[mf], stA + ((abase[mf] + ks * 32) ^ amask[mf]));
            #pragma unroll
            for (int q = 0; q < 4; q++)
                LDSM4(rb[q], stB + ((bbase[q] + ks * 32) ^ bmask[q]));
            #pragma unroll
            for (int mf = 0; mf < 4; mf++)
                #pragma unroll
                for (int nf = 0; nf < 7; nf++)
                    MMA(acc[mf][nf], ra[mf], rb[nf >> 1][(nf & 1) * 2], rb[nf >> 1][(nf & 1) * 2 + 1]);
        }

        MBAR_ARRIVE(sb + 32 + cs * 8);
        cs++; if (cs == NSTG){ cs = 0; cph ^= 1; }

        if (tid == 0 && pn < NCH){
            MBAR_WAIT(sb + 32 + ps * 8, pph);      // stage drained by all consumers
            issue_chunk(pn, ps, data, sb, img, t, &mW, &mX);
            pn++; ps++; if (ps == NSTG){ ps = 0; pph ^= 1; }
        }
    }

    // ---- epilogue: fp32 alpha scale; all outputs valid, unconditional ----
    float* outp = out + (size_t)img * Oo * MIMG;
    const int mrow = (2 * t + wp) * Ww;
    #pragma unroll
    for (int mf = 0; mf < 4; mf++){
        const int oc0 = wo * 64 + mf * 16 + (l >> 2);
        const float a0 = __ldg(&g_alpha[oc0]);
        const float a1 = __ldg(&g_alpha[oc0 + 8]);
        #pragma unroll
        for (int nf = 0; nf < 7; nf++){
            const int m = mrow + nf * 8 + 2 * (l & 3);
            float2 v0 = make_float2(acc[mf][nf][0] * a0, acc[mf][nf][1] * a0);
            float2 v1 = make_float2(acc[mf][nf][2] * a1, acc[mf][nf][3] * a1);
            *reinterpret_cast<float2*>(outp + (size_t)oc0 * MIMG + m)       = v0;
            *reinterpret_cast<float2*>(outp + (size_t)(oc0 + 8) * MIMG + m) = v1;
        }
    }
}

// ---------------------------------------------------------------------------
typedef CUresult (*PFN_tmEnc)(CUtensorMap*, CUtensorMapDataType, cuuint32_t, void*,
                              const cuuint64_t*, const cuuint64_t*, const cuuint32_t*,
                              const cuuint32_t*, CUtensorMapInterleave, CUtensorMapSwizzle,
                              CUtensorMapL2promotion, CUtensorMapFloatOOBfill);

extern "C" void kernel_launch(void* const* d_in, const int* in_sizes, int n_in,
                              void* d_out, int out_size){
    const float* x = (const float*)d_in[0];
    const float* w = (const float*)d_in[1];
    if (n_in >= 2 && in_sizes[0] == Oo * KT && in_sizes[1] != Oo * KT){
        x = (const float*)d_in[1];
        w = (const float*)d_in[0];
    }

    void *pxh = nullptr, *pw = nullptr;
    cudaGetSymbolAddress(&pxh, g_xh);
    cudaGetSymbolAddress(&pw,  g_bsign);

    PFN_tmEnc enc = nullptr;
    cudaDriverEntryPointQueryResult qr;
    cudaGetDriverEntryPointByVersion("cuTensorMapEncodeTiled", (void**)&enc, 12000,
                                     cudaEnableDefault, &qr);

    CUtensorMap mW, mX;
    {   // signs: 2D [k=2304][oc=256], box (64, 256), SW128
        cuuint64_t dim[2]   = {KT, Oo};
        cuuint64_t strd[1]  = {KT * 2};
        cuuint32_t box[2]   = {64, 256};
        cuuint32_t est[2]   = {1, 1};
        enc(&mW, CU_TENSOR_MAP_DATA_TYPE_FLOAT16, 2, pw, dim, strd, box, est,
            CU_TENSOR_MAP_INTERLEAVE_NONE, CU_TENSOR_MAP_SWIZZLE_128B,
            CU_TENSOR_MAP_L2_PROMOTION_L2_128B, CU_TENSOR_MAP_FLOAT_OOB_FILL_NONE);
    }
    {   // x plane: 3D [c=256][w=64][img*h=1856], box (64, 64, 2), SW128
        cuuint64_t dim[3]   = {Cc, WP, (cuuint64_t)NIMG * HP};
        cuuint64_t strd[2]  = {Cc * 2, (cuuint64_t)WP * Cc * 2};
        cuuint32_t box[3]   = {64, 64, 2};
        cuuint32_t est[3]   = {1, 1, 1};
        enc(&mX, CU_TENSOR_MAP_DATA_TYPE_FLOAT16, 3, pxh, dim, strd, box, est,
            CU_TENSOR_MAP_INTERLEAVE_NONE, CU_TENSOR_MAP_SWIZZLE_128B,
            CU_TENSOR_MAP_L2_PROMOTION_L2_128B, CU_TENSOR_MAP_FLOAT_OOB_FILL_NONE);
    }

    cudaFuncSetAttribute(conv_mma, cudaFuncAttributeMaxDynamicSharedMemorySize, SMEM_TOTAL);

    prologue_kernel<<<dim3(49, 8, NIMG + 1), 256>>>(x, w);
    conv_mma<<<dim3(28, NIMG), 256, SMEM_TOTAL>>>(mW, mX, (float*)d_out);
}